// round 4
// baseline (speedup 1.0000x reference)
#include <cuda_runtime.h>
#include <cuda_fp16.h>

#define CH 16
#define RES 512
#define PLANE_TEX (RES * RES)

// Quad-block packed fp16 features, 4 parity-shifted copies:
//   g_pack[copy(4)][plane(3)][X(256)][Y(256)] -> 128B block = [ch16][dx2][dy2] half
// copy = xoff*2 + yoff; block (X,Y) of copy holds texels (2X+xoff + dx, 2Y+yoff + dy).
// Any bilinear footprint (xi..xi+1, yi..yi+1) is exactly ONE 128B block of
// copy ((xi&1)<<1)|(yi&1). Total: 4 * 3*256*256 * 128B = 100.6 MB (L2-resident).
__device__ __align__(16) __half g_pack[4ull * 3 * 256 * 256 * 64];

// ---------------------------------------------------------------------------
// Pack kernel: one thread per output block. idx = ((copy*3+p)*256 + X)*256 + Y.
// Reads 16ch x 4 texels (clamped at 511 edge; those blocks are never sampled),
// writes one 128B block with 8 coalesced-enough STG.128.
// ---------------------------------------------------------------------------
__global__ void __launch_bounds__(256) pack_k(const float* __restrict__ fm) {
    int idx = blockIdx.x * 256 + threadIdx.x;   // 0 .. 4*3*256*256-1
    int Y   = idx & 255;
    int X   = (idx >> 8) & 255;
    int cp3 = idx >> 16;                        // copy*3 + p, 0..11
    int copy = cp3 / 3;
    int p    = cp3 - copy * 3;
    int xoff = copy >> 1, yoff = copy & 1;

    int x0 = 2 * X + xoff;
    int x1 = min(x0 + 1, RES - 1);
    int y0 = 2 * Y + yoff;
    int y1 = min(y0 + 1, RES - 1);

    union Blk { __half2 h[32]; uint4 u[8]; };
    Blk b;
#pragma unroll
    for (int c = 0; c < CH; ++c) {
        const float* ch = fm + (size_t)(p * CH + c) * PLANE_TEX;
        float f00 = __ldcs(ch + x0 * RES + y0);
        float f01 = __ldcs(ch + x0 * RES + y1);
        float f10 = __ldcs(ch + x1 * RES + y0);
        float f11 = __ldcs(ch + x1 * RES + y1);
        b.h[c * 2 + 0] = __halves2half2(__float2half_rn(f00), __float2half_rn(f01));
        b.h[c * 2 + 1] = __halves2half2(__float2half_rn(f10), __float2half_rn(f11));
    }

    uint4* dst = reinterpret_cast<uint4*>(g_pack + (size_t)idx * 64);
#pragma unroll
    for (int i = 0; i < 8; ++i) dst[i] = b.u[i];
}

// ---------------------------------------------------------------------------
// Sampling: FOUR threads per (point, plane); lane q owns channels 4q..4q+3.
// One parity copy lookup -> the whole 2x2 bilinear footprint is a single
// 128B line; lane q loads its 32B as 2 LDG.128 from that line.
// No division (scale folded into one FMA); one address chain.
// ---------------------------------------------------------------------------
__global__ void __launch_bounds__(256) sample_k(const float* __restrict__ xyz,
                                                float* __restrict__ out, int nPP) {
    int g  = blockIdx.x * 256 + threadIdx.x;
    int pp = g >> 2;
    int q  = g & 3;
    if (pp >= nPP) return;
    int n  = pp / 3;
    int pl = pp - n * 3;

    float X = __ldg(xyz + 3 * n + 0);
    float Y = __ldg(xyz + 3 * n + 1);
    float Z = __ldg(xyz + 3 * n + 2);

    // (c/s + 1) * 255.5 ; s=0.05 folded: 255.5/0.05 = 5110 (exact in fp32).
    // pl 0: planes[0], (x, y); pl 1: planes[2], (y, z/s); pl 2: planes[1], (z/s, x)
    float x, y; int fp;
    if (pl == 0)      { x = fmaf(X, 255.5f, 255.5f);  y = fmaf(Y, 255.5f, 255.5f);  fp = 0; }
    else if (pl == 1) { x = fmaf(Y, 255.5f, 255.5f);  y = fmaf(Z, 5110.0f, 255.5f); fp = 2; }
    else              { x = fmaf(Z, 5110.0f, 255.5f); y = fmaf(X, 255.5f, 255.5f);  fp = 1; }

    float x0f = floorf(x), y0f = floorf(y);
    float fx = x - x0f;   // exact
    float fy = y - y0f;
    float gx = 1.0f - fx;
    float gy = 1.0f - fy;

    float wa = gx * gy;   // (x0, y0)
    float wb = fx * gy;   // (x1, y0)
    float wc = gx * fy;   // (x0, y1)
    float wd = fx * fy;   // (x1, y1)

    int xi = min(max((int)x0f, 0), RES - 2);
    int yi = min(max((int)y0f, 0), RES - 2);

    int copy = ((xi & 1) << 1) | (yi & 1);
    int Xi = xi >> 1, Yi = yi >> 1;

    // halves: block index = ((copy*3+fp)<<16) | (Xi<<8) | Yi, 64 halves/block
    int blk = (((copy * 3 + fp) << 8 | Xi) << 8) | Yi;
    const __half* ptr = g_pack + (size_t)blk * 64 + q * 16;

    uint4 u0 = __ldg(reinterpret_cast<const uint4*>(ptr));       // ch 4q, 4q+1
    uint4 u1 = __ldg(reinterpret_cast<const uint4*>(ptr + 8));   // ch 4q+2, 4q+3

    const __half2* h0 = reinterpret_cast<const __half2*>(&u0);
    const __half2* h1 = reinterpret_cast<const __half2*>(&u1);

    float4 r;
#define CHV(hsrc, k, dst) {                                               \
        float2 a = __half22float2(hsrc[2*(k)]);     /* (x0y0, x0y1) */    \
        float2 b = __half22float2(hsrc[2*(k)+1]);   /* (x1y0, x1y1) */    \
        dst = wa * a.x + wc * a.y + wb * b.x + wd * b.y; }
    CHV(h0, 0, r.x)
    CHV(h0, 1, r.y)
    CHV(h1, 0, r.z)
    CHV(h1, 1, r.w)
#undef CHV

    __stcs(reinterpret_cast<float4*>(out) + (size_t)pp * 4 + q, r);
}

extern "C" void kernel_launch(void* const* d_in, const int* in_sizes, int n_in,
                              void* d_out, int out_size) {
    const float* xyz = (const float*)d_in[0];   // (N, 3) float32
    const float* fm  = (const float*)d_in[1];   // (48, 512, 512) float32
    float* out = (float*)d_out;                 // (N, 48) float32
    int N = in_sizes[0] / 3;
    int nPP = N * 3;
    long long threads = (long long)nPP * 4;
    int blocks = (int)((threads + 255) / 256);

    pack_k<<<(4 * 3 * 256 * 256) / 256, 256>>>(fm);
    sample_k<<<blocks, 256>>>(xyz, out, nPP);
}

// round 5
// speedup vs baseline: 1.2371x; 1.2371x over previous
#include <cuda_runtime.h>
#include <cuda_fp16.h>

#define CH 16
#define RES 512
#define PLANE_TEX (RES * RES)

// Packed, y-pair-interleaved, fp16, two shifted copies (50.3 MB, L2-resident):
//   g_pack[copy(2)][plane(3)][x(512)][Y(256)][ch(16)][dy(2)]  (__half)
// copy 0: Y-block holds rows (2Y, 2Y+1); copy 1: (2Y+1, 2Y+2).
// One 64B block per (x, y-pair) -> a sample's row fetch is ONE aligned line.
__device__ __align__(16) __half g_pack[2u * 3 * 512 * 256 * 32];

#define COPY_STRIDE (3 * 512 * 256 * 32)   // halves per copy
#define ROW_STRIDE  (256 * 32)             // halves per x-row

// ---------------------------------------------------------------------------
// Pack kernel: one thread per (plane, x, Y). Reads y = 2Y, 2Y+1, 2Y+2 for all
// 16 channels, writes both copies' blocks (half2 per channel = (y0, y1)).
// ---------------------------------------------------------------------------
__global__ void __launch_bounds__(256) pack_k(const float* __restrict__ fm) {
    int idx = blockIdx.x * 256 + threadIdx.x;   // 0 .. 3*512*256-1
    int Y  = idx & 255;
    int px = idx >> 8;                          // p*512 + x
    int p  = px >> 9;
    int x  = px & 511;

    const float* src = fm + (size_t)p * (CH * PLANE_TEX) + (size_t)x * RES + 2 * Y;

    union Blk { __half2 h[16]; uint4 u[4]; };
    Blk b0, b1;
#pragma unroll
    for (int c = 0; c < CH; ++c) {
        const float* s = src + (size_t)c * PLANE_TEX;
        float f0 = __ldcs(s);
        float f1 = __ldcs(s + 1);
        float f2 = (Y < 255) ? __ldcs(s + 2) : f1;   // Y=255 copy1 never sampled
        __half h0 = __float2half_rn(f0);
        __half h1 = __float2half_rn(f1);
        __half h2 = __float2half_rn(f2);
        b0.h[c] = __halves2half2(h0, h1);
        b1.h[c] = __halves2half2(h1, h2);
    }

    uint4* d0 = reinterpret_cast<uint4*>(g_pack + (size_t)idx * 32);
    uint4* d1 = reinterpret_cast<uint4*>(g_pack + COPY_STRIDE + (size_t)idx * 32);
#pragma unroll
    for (int i = 0; i < 4; ++i) { d0[i] = b0.u[i]; d1[i] = b1.u[i]; }
}

// ---------------------------------------------------------------------------
// Sampling: FOUR threads per (point, plane); lane q owns channels 4q..4q+3.
// Division-free coords (scale folded: 255.5/0.05 = 5110 exact). Each lane does
// 2x LDG.128 (rows xi, xi+1); 4 lanes of a pp coalesce to one 64B block per
// row -> 1 L1 wavefront per row per pp. Stores fully coalesced (float4 at g).
// ---------------------------------------------------------------------------
__global__ void __launch_bounds__(256) sample_k(const float* __restrict__ xyz,
                                                float* __restrict__ out, int nPP) {
    int g  = blockIdx.x * 256 + threadIdx.x;
    int pp = g >> 2;
    int q  = g & 3;
    if (pp >= nPP) return;
    int n  = pp / 3;
    int pl = pp - n * 3;

    float X = __ldg(xyz + 3 * n + 0);
    float Y = __ldg(xyz + 3 * n + 1);
    float Z = __ldg(xyz + 3 * n + 2);

    // (c/s + 1) * 255.5 ; s=0.05 folded exactly into the FMA constant.
    // pl 0: planes[0], (x, y); pl 1: planes[2], (y, z/s); pl 2: planes[1], (z/s, x)
    float x, y; int fp;
    if (pl == 0)      { x = fmaf(X, 255.5f, 255.5f);  y = fmaf(Y, 255.5f, 255.5f);  fp = 0; }
    else if (pl == 1) { x = fmaf(Y, 255.5f, 255.5f);  y = fmaf(Z, 5110.0f, 255.5f); fp = 2; }
    else              { x = fmaf(Z, 5110.0f, 255.5f); y = fmaf(X, 255.5f, 255.5f);  fp = 1; }

    float x0f = floorf(x), y0f = floorf(y);
    float fx = x - x0f;   // exact
    float fy = y - y0f;
    float gx = 1.0f - fx;
    float gy = 1.0f - fy;

    float wa = gx * gy;   // (x0, y0)
    float wb = fx * gy;   // (x1, y0)
    float wc = gx * fy;   // (x0, y1)
    float wd = fx * fy;   // (x1, y1)

    int xi = min(max((int)x0f, 0), RES - 2);
    int yi = min(max((int)y0f, 0), RES - 2);

    int copy = yi & 1;
    int Yi   = yi >> 1;   // block rows = (yi, yi+1) in both parities

    // halves offset: [copy][fp][xi][Yi] blocks of 32 halves; lane piece +q*8
    int base = ((((copy * 3 + fp) << 9) + xi) * 256 + Yi) * 32 + q * 8;

    uint4 u0 = __ldg(reinterpret_cast<const uint4*>(g_pack + base));               // row xi
    uint4 u1 = __ldg(reinterpret_cast<const uint4*>(g_pack + base + ROW_STRIDE));  // row xi+1

    const __half2* h0 = reinterpret_cast<const __half2*>(&u0);
    const __half2* h1 = reinterpret_cast<const __half2*>(&u1);

    float4 r;
#define CHV(c, dst) {                                                   \
        float2 a = __half22float2(h0[c]);  /* (y0, y1) @ row xi   */    \
        float2 b = __half22float2(h1[c]);  /* (y0, y1) @ row xi+1 */    \
        dst = wa * a.x + wc * a.y + wb * b.x + wd * b.y; }
    CHV(0, r.x)
    CHV(1, r.y)
    CHV(2, r.z)
    CHV(3, r.w)
#undef CHV

    __stcs(reinterpret_cast<float4*>(out) + (size_t)pp * 4 + q, r);
}

extern "C" void kernel_launch(void* const* d_in, const int* in_sizes, int n_in,
                              void* d_out, int out_size) {
    const float* xyz = (const float*)d_in[0];   // (N, 3) float32
    const float* fm  = (const float*)d_in[1];   // (48, 512, 512) float32
    float* out = (float*)d_out;                 // (N, 48) float32
    int N = in_sizes[0] / 3;
    int nPP = N * 3;
    long long threads = (long long)nPP * 4;
    int blocks = (int)((threads + 255) / 256);

    pack_k<<<(3 * 512 * 256) / 256, 256>>>(fm);
    sample_k<<<blocks, 256>>>(xyz, out, nPP);
}

// round 6
// speedup vs baseline: 1.5689x; 1.2682x over previous
#include <cuda_runtime.h>
#include <cuda_fp16.h>

#define CH 16
#define RES 512
#define PLANE_TEX (RES * RES)

// Packed, y-pair-interleaved, fp16, two shifted copies (50.3 MB, L2-resident):
//   g_pack[copy(2)][plane(3)][x(512)][Y(256)][ch(16)][dy(2)]  (__half)
// copy 0: Y-block = rows (2Y, 2Y+1); copy 1: rows (2Y+1, 2Y+2).
__device__ __align__(16) __half g_pack[2u * 3 * 512 * 256 * 32];

#define COPY_STRIDE (3 * 512 * 256 * 32)   // halves per copy
#define ROW_STRIDE  (256 * 32)             // halves per x-row

// ---------------------------------------------------------------------------
// Pack kernel (unchanged from R5).
// ---------------------------------------------------------------------------
__global__ void __launch_bounds__(256) pack_k(const float* __restrict__ fm) {
    int idx = blockIdx.x * 256 + threadIdx.x;
    int Y  = idx & 255;
    int px = idx >> 8;
    int p  = px >> 9;
    int x  = px & 511;

    const float* src = fm + (size_t)p * (CH * PLANE_TEX) + (size_t)x * RES + 2 * Y;

    union Blk { __half2 h[16]; uint4 u[4]; };
    Blk b0, b1;
#pragma unroll
    for (int c = 0; c < CH; ++c) {
        const float* s = src + (size_t)c * PLANE_TEX;
        float f0 = __ldcs(s);
        float f1 = __ldcs(s + 1);
        float f2 = (Y < 255) ? __ldcs(s + 2) : f1;
        __half h0 = __float2half_rn(f0);
        __half h1 = __float2half_rn(f1);
        __half h2 = __float2half_rn(f2);
        b0.h[c] = __halves2half2(h0, h1);
        b1.h[c] = __halves2half2(h1, h2);
    }

    uint4* d0 = reinterpret_cast<uint4*>(g_pack + (size_t)idx * 32);
    uint4* d1 = reinterpret_cast<uint4*>(g_pack + COPY_STRIDE + (size_t)idx * 32);
#pragma unroll
    for (int i = 0; i < 4; ++i) { d0[i] = b0.u[i]; d1[i] = b1.u[i]; }
}

// Phase A for one pp: coords -> weights (packed half2) + issue the two row loads.
// pl/fp/scale selection is hoisted out (same for paired pps).
__device__ __forceinline__ void phaseA(int n, int fp, float s0, float s1,
                                       int src0, int q,
                                       const float* __restrict__ xyz,
                                       uint4& u0, uint4& u1,
                                       __half2& wac, __half2& wbd) {
    float X = __ldg(xyz + 3 * n + 0);
    float Y = __ldg(xyz + 3 * n + 1);
    float Z = __ldg(xyz + 3 * n + 2);

    // src0: 0 -> (X,Y), 1 -> (Y,Z), 2 -> (Z,X)
    float c0 = (src0 == 0) ? X : (src0 == 1) ? Y : Z;
    float c1 = (src0 == 0) ? Y : (src0 == 1) ? Z : X;

    float x = fmaf(c0, s0, 255.5f);
    float y = fmaf(c1, s1, 255.5f);

    int ix = __float2int_rd(x);            // floor as int, 1 instr
    int iy = __float2int_rd(y);
    float fx = x - __int2float_rn(ix);     // unclamped frac (matches reference)
    float fy = y - __int2float_rn(iy);
    float gx = 1.0f - fx;
    float gy = 1.0f - fy;

    wac = __floats2half2_rn(gx * gy, gx * fy);   // (wa, wc) for row xi
    wbd = __floats2half2_rn(fx * gy, fx * fy);   // (wb, wd) for row xi+1

    int xi = min(max(ix, 0), RES - 2);
    int yi = min(max(iy, 0), RES - 2);
    int copy = yi & 1;
    int Yi   = yi >> 1;

    int base = ((((copy * 3 + fp) << 9) + xi) * 256 + Yi) * 32 + q * 8;
    u0 = __ldg(reinterpret_cast<const uint4*>(g_pack + base));               // row xi
    u1 = __ldg(reinterpret_cast<const uint4*>(g_pack + base + ROW_STRIDE));  // row xi+1
}

// Phase B: fp16 partial blend (hmul2/hfma2), fp32 horizontal add.
__device__ __forceinline__ float4 phaseB(const uint4& u0, const uint4& u1,
                                         __half2 wac, __half2 wbd) {
    const __half2* h0 = reinterpret_cast<const __half2*>(&u0);
    const __half2* h1 = reinterpret_cast<const __half2*>(&u1);
    float4 r;
#define CHV(c, dst) {                                         \
        __half2 p = __hmul2(h0[c], wac);                      \
        p = __hfma2(h1[c], wbd, p);                           \
        float2 f = __half22float2(p);                         \
        dst = f.x + f.y; }
    CHV(0, r.x)
    CHV(1, r.y)
    CHV(2, r.z)
    CHV(3, r.w)
#undef CHV
    return r;
}

// ---------------------------------------------------------------------------
// Paired sampler: thread t handles pp0 = t>>2 and pp1 = pp0 + H (H = nPP/2,
// divisible by 3) with lane q = t&3 owning channels 4q..4q+3. Both pps share
// pl -> one divide + one select chain. All 4 texel loads in flight before the
// first blend. Store index for pp0 is exactly t; pp1 is t + 4H.
// ---------------------------------------------------------------------------
__global__ void __launch_bounds__(256) sample2_k(const float* __restrict__ xyz,
                                                 float4* __restrict__ out4, int nPP) {
    int t = blockIdx.x * 256 + threadIdx.x;
    int H = nPP >> 1;                       // divisible by 3 (checked host-side)
    int pp0 = t >> 2;
    int q   = t & 3;
    if (pp0 >= H) return;

    int n0 = pp0 / 3;
    int pl = pp0 - n0 * 3;
    int n1 = n0 + H / 3;                    // pp1 = pp0 + H has same pl

    // pl 0: planes[0], (X,Y);  pl 1: planes[2], (Y, Z*20);  pl 2: planes[1], (Z*20, X)
    int   fp = (pl == 0) ? 0 : (pl == 1) ? 2 : 1;
    float s0 = (pl == 2) ? 5110.0f : 255.5f;   // 255.5/0.05 = 5110 exact
    float s1 = (pl == 1) ? 5110.0f : 255.5f;

    uint4 a0, a1, b0, b1;
    __half2 wacA, wbdA, wacB, wbdB;
    phaseA(n0, fp, s0, s1, pl, q, xyz, a0, a1, wacA, wbdA);
    phaseA(n1, fp, s0, s1, pl, q, xyz, b0, b1, wacB, wbdB);

    float4 rA = phaseB(a0, a1, wacA, wbdA);
    float4 rB = phaseB(b0, b1, wacB, wbdB);

    __stcs(out4 + t, rA);
    __stcs(out4 + (size_t)t + (size_t)4 * H, rB);
}

// Fallback single-pp sampler (used only if nPP % 6 != 0).
__global__ void __launch_bounds__(256) sample1_k(const float* __restrict__ xyz,
                                                 float4* __restrict__ out4, int nPP) {
    int t = blockIdx.x * 256 + threadIdx.x;
    int pp = t >> 2;
    int q  = t & 3;
    if (pp >= nPP) return;

    int n  = pp / 3;
    int pl = pp - n * 3;
    int   fp = (pl == 0) ? 0 : (pl == 1) ? 2 : 1;
    float s0 = (pl == 2) ? 5110.0f : 255.5f;
    float s1 = (pl == 1) ? 5110.0f : 255.5f;

    uint4 u0, u1;
    __half2 wac, wbd;
    phaseA(n, fp, s0, s1, pl, q, xyz, u0, u1, wac, wbd);
    float4 r = phaseB(u0, u1, wac, wbd);
    __stcs(out4 + t, r);
}

extern "C" void kernel_launch(void* const* d_in, const int* in_sizes, int n_in,
                              void* d_out, int out_size) {
    const float* xyz = (const float*)d_in[0];   // (N, 3) float32
    const float* fm  = (const float*)d_in[1];   // (48, 512, 512) float32
    float4* out4 = (float4*)d_out;              // (N, 48) float32 = (N*3, 4) float4-lanes
    int N = in_sizes[0] / 3;
    int nPP = N * 3;

    pack_k<<<(3 * 512 * 256) / 256, 256>>>(fm);

    if (nPP % 6 == 0) {
        long long threads = (long long)nPP * 2;   // 4 lanes x nPP/2 pairs
        int blocks = (int)((threads + 255) / 256);
        sample2_k<<<blocks, 256>>>(xyz, out4, nPP);
    } else {
        long long threads = (long long)nPP * 4;
        int blocks = (int)((threads + 255) / 256);
        sample1_k<<<blocks, 256>>>(xyz, out4, nPP);
    }
}